// round 4
// baseline (speedup 1.0000x reference)
#include <cuda_runtime.h>
#include <cstdint>

// Math after collapse (verified, rel_err ~9e-7):
//   attn == 1/H exactly (softmax over an exactly-broadcast head axis)
//   sv[b,j]  = <sum_q v[b,q,:], Wv[j,:]> + Sq*bv[j]
//   row[b,d] = (1/H) * <sv[b,:], Wb[d,:]> + bb[d]
//   out[s,b,d] = row[b,d]  for all s
static constexpr int B  = 4;
static constexpr int SQ = 1024;
static constexpr int SK = 1024;
static constexpr int D  = 1024;
static constexpr int DH = 64;
static constexpr int H  = 16;

static constexpr int QS = 32;            // q-splits -> B*QS = 128 blocks (single wave)

// Scratch (__device__ globals; no allocation allowed)
__device__ float g_partial[QS * B * D];      // 512 KB: per-(qs,b) partial row sums
__device__ float g_svp[4 * B * DH];          // 4 KB: per-d-chunk partial sv
__device__ float g_row[B * D];               // 16 KB: final per-(b,d) row

// ---------------------------------------------------------------------------
// A: column-sum v over Sq. grid (B, QS)=128 blocks x 1024 threads.
// 4 strips of 256 threads; strip s sums 8 rows; smem combine. Single wave.
// ---------------------------------------------------------------------------
__global__ void __launch_bounds__(1024) reduce_v_kernel(const float* __restrict__ v) {
    const int b     = blockIdx.x;
    const int qs    = blockIdx.y;
    const int t     = threadIdx.x;
    const int t4    = t & 255;          // d-slot (float4)
    const int strip = t >> 8;           // 0..3

    const float4* vb = reinterpret_cast<const float4*>(v + (size_t)b * SQ * D);
    const int q0 = qs * 32 + strip * 8;

    float4 acc = make_float4(0.f, 0.f, 0.f, 0.f);
#pragma unroll
    for (int r = 0; r < 8; ++r) {
        float4 x = vb[(size_t)(q0 + r) * (D / 4) + t4];
        acc.x += x.x; acc.y += x.y; acc.z += x.z; acc.w += x.w;
    }

    __shared__ float4 sred[4][256];     // 16 KB
    sred[strip][t4] = acc;
    __syncthreads();

    if (strip == 0) {
        float4 a0 = sred[0][t4], a1 = sred[1][t4], a2 = sred[2][t4], a3 = sred[3][t4];
        float4 s;
        s.x = (a0.x + a1.x) + (a2.x + a3.x);
        s.y = (a0.y + a1.y) + (a2.y + a3.y);
        s.z = (a0.z + a1.z) + (a2.z + a3.z);
        s.w = (a0.w + a1.w) + (a2.w + a3.w);
        reinterpret_cast<float4*>(g_partial)[(size_t)(qs * B + b) * (D / 4) + t4] = s;
    }
}

// ---------------------------------------------------------------------------
// B1: finish vsum per 256-float d-chunk, project through Wv.
// grid (B, 4) x 256 threads.
// ---------------------------------------------------------------------------
__global__ void __launch_bounds__(256) gemv1_kernel(const float* __restrict__ Wv) {
    const int b = blockIdx.x;
    const int c = blockIdx.y;           // d-chunk index, 0..3
    const int t = threadIdx.x;

    const int slot = t & 63;            // float4 slot within chunk (64 slots)
    const int qsub = t >> 6;            // 0..3: split over qs

    float4 acc = make_float4(0.f, 0.f, 0.f, 0.f);
#pragma unroll
    for (int q = qsub; q < QS; q += 4) {
        float4 x = reinterpret_cast<const float4*>(g_partial)
                       [(size_t)(q * B + b) * (D / 4) + c * 64 + slot];
        acc.x += x.x; acc.y += x.y; acc.z += x.z; acc.w += x.w;
    }

    __shared__ float4 sred[256];
    __shared__ float  s_v[256];         // vsum for this chunk
    sred[t] = acc;
    __syncthreads();
    if (qsub == 0) {
        float4 a0 = sred[slot], a1 = sred[64 + slot], a2 = sred[128 + slot], a3 = sred[192 + slot];
        float4 s;
        s.x = (a0.x + a1.x) + (a2.x + a3.x);
        s.y = (a0.y + a1.y) + (a2.y + a3.y);
        s.z = (a0.z + a1.z) + (a2.z + a3.z);
        s.w = (a0.w + a1.w) + (a2.w + a3.w);
        reinterpret_cast<float4*>(s_v)[slot] = s;
    }
    __syncthreads();

    const int warp = t >> 5, lane = t & 31;
#pragma unroll
    for (int jj = 0; jj < 8; ++jj) {
        const int j = warp * 8 + jj;
        const float* wr = Wv + (size_t)j * D + c * 256;
        float s = 0.f;
#pragma unroll
        for (int i = 0; i < 8; ++i) s += s_v[lane + i * 32] * wr[lane + i * 32];
#pragma unroll
        for (int o = 16; o > 0; o >>= 1) s += __shfl_xor_sync(0xFFFFFFFFu, s, o);
        if (lane == 0) g_svp[(c * B + b) * DH + j] = s;
    }
}

// ---------------------------------------------------------------------------
// B2: sv = sum of 4 chunk-partials + Sq*bv; row = (1/H)*sv.Wb^T + bb.
// grid (B, 4) x 256 threads.
// ---------------------------------------------------------------------------
__global__ void __launch_bounds__(256) gemv2_kernel(const float* __restrict__ bv,
                                                    const float* __restrict__ Wb,
                                                    const float* __restrict__ bb) {
    const int b = blockIdx.x;
    const int c = blockIdx.y;
    const int t = threadIdx.x;

    __shared__ float s_sv[DH];
    if (t < DH) {
        float s = (float)SQ * bv[t];
        s += ((g_svp[(0 * B + b) * DH + t] + g_svp[(1 * B + b) * DH + t])
            + (g_svp[(2 * B + b) * DH + t] + g_svp[(3 * B + b) * DH + t]));
        s_sv[t] = s;
    }
    __syncthreads();

    const int d = c * 256 + t;
    const float4* wb = reinterpret_cast<const float4*>(Wb + (size_t)d * DH);
    float s = 0.f;
#pragma unroll
    for (int j4 = 0; j4 < DH / 4; ++j4) {
        float4 w = wb[j4];
        s += s_sv[j4 * 4 + 0] * w.x + s_sv[j4 * 4 + 1] * w.y
           + s_sv[j4 * 4 + 2] * w.z + s_sv[j4 * 4 + 3] * w.w;
    }
    g_row[b * D + d] = s * (1.0f / (float)H) + bb[d];
}

// ---------------------------------------------------------------------------
// C: broadcast via TMA bulk stores. Each block loads the 16 KB row tile into
// smem once, then one elected thread issues COPIES_PER_BLOCK bulk copies of
// the full tile to distinct 16 KB output segments. The TMA engine drives L2
// at chip throughput; per-block issue cost is ~4 instructions.
// ---------------------------------------------------------------------------
static constexpr int ROW_BYTES        = B * D * 4;               // 16384
static constexpr int C_BLOCKS         = 256;
static constexpr int COPIES_PER_BLOCK = SK / C_BLOCKS;           // 4

__global__ void __launch_bounds__(256) bcast_tma_kernel(char* __restrict__ out) {
    __shared__ __align__(128) float s_row[B * D];   // 16 KB

    for (int i = threadIdx.x; i < B * D / 4; i += 256)
        reinterpret_cast<float4*>(s_row)[i] = reinterpret_cast<const float4*>(g_row)[i];
    __syncthreads();
    // make generic-proxy smem writes visible to the async (TMA) proxy
    asm volatile("fence.proxy.async.shared::cta;" ::: "memory");

    if (threadIdx.x == 0) {
        uint32_t saddr;
        asm("{ .reg .u64 tmp; cvta.to.shared.u64 tmp, %1; cvt.u32.u64 %0, tmp; }"
            : "=r"(saddr) : "l"(s_row));
        char* base = out + (size_t)blockIdx.x * COPIES_PER_BLOCK * ROW_BYTES;
#pragma unroll
        for (int c = 0; c < COPIES_PER_BLOCK; ++c) {
            asm volatile(
                "cp.async.bulk.global.shared::cta.bulk_group [%0], [%1], %2;"
                :: "l"(base + (size_t)c * ROW_BYTES), "r"(saddr), "r"(ROW_BYTES)
                : "memory");
        }
        asm volatile("cp.async.bulk.commit_group;" ::: "memory");
        asm volatile("cp.async.bulk.wait_group 0;" ::: "memory");
    }
}

extern "C" void kernel_launch(void* const* d_in, const int* in_sizes, int n_in,
                              void* d_out, int out_size) {
    // Inputs: 0=q 1=k 2=h 3=w 4=v 5=Wq 6=bq 7=Wk 8=bk 9=Wv 10=bv 11=Wb 12=bb
    const float* v  = (const float*)d_in[4];
    const float* Wv = (const float*)d_in[9];
    const float* bv = (const float*)d_in[10];
    const float* Wb = (const float*)d_in[11];
    const float* bb = (const float*)d_in[12];

    reduce_v_kernel<<<dim3(B, QS), 1024>>>(v);
    gemv1_kernel<<<dim3(B, 4), 256>>>(Wv);
    gemv2_kernel<<<dim3(B, 4), 256>>>(bv, Wb, bb);
    bcast_tma_kernel<<<C_BLOCKS, 256>>>((char*)d_out);
}